// round 2
// baseline (speedup 1.0000x reference)
#include <cuda_runtime.h>

typedef unsigned int u32;
typedef unsigned char u8;

#define EPSBN 1e-5f
#define NIMG 64
#define C1 512
#define C2 128
#define C3 32
#define HW 784
#define PTOT (NIMG*HW)   // 50176

// ---------------- device scratch (allocations forbidden) ----------------
__device__ u32   g_mm[8];                    // encoded min/max atomics: [0,1]=a1 [2,3]=w1 [4,5]=w2 [6,7]=a2
__device__ float g_qp[12];                   // [mn,s,rcp] x {a1,w1,w2,a2}
__device__ u32   g_wq1_32[C2*C1/4];          // quantized w1, packed 4 ci per u32, [co][128]
__device__ int   g_ws1[C2];                  // per-co weight index sums (w1)
__device__ u32   g_wq2t[9*32*32];            // quantized w2, [tap*32+kg][co] packed u32 (4 ci)
__device__ int   g_wts2[C3*9];               // per-(co,tap) weight index sums (w2)
__device__ float g_a2[(size_t)PTOT*C2];      // relu(bn2(h)) fp32, NHWC  (25.7MB)
__device__ u32   g_aq2[(size_t)PTOT*32];     // quantized a2, packed u8x4, NHWC (6.4MB)
__device__ int   g_rs2[PTOT];                // per-pixel sum of a2 indices

// ---------------- helpers ----------------
__device__ __forceinline__ u32 fenc(float f){
    u32 u = __float_as_uint(f);
    return (u & 0x80000000u) ? ~u : (u | 0x80000000u);
}
__device__ __forceinline__ float fdec(u32 e){
    return __uint_as_float((e & 0x80000000u) ? (e & 0x7fffffffu) : ~e);
}
// quant index: correctly-rounded (v-mn)/s via Markstein refinement, then rn-to-int
__device__ __forceinline__ int qidx(float v, float mn, float s, float r){
    float t  = __fsub_rn(v, mn);
    float q0 = __fmul_rn(t, r);
    float q  = __fmaf_rn(__fmaf_rn(-s, q0, t), r, q0);
    int i = __float2int_rn(q);
    i = i < 0 ? 0 : i;
    return i > 255 ? 255 : i;
}

// ---------------- kernels ----------------
__global__ void k_init(){
    int t = threadIdx.x;
    if (t < 8) g_mm[t] = (t & 1) ? 0u : 0xFFFFFFFFu;
}

// min/max of relu(bn1(x))
__global__ void k_mm_a1(const float* __restrict__ x, const float* __restrict__ g1,
                        const float* __restrict__ b1, const float* __restrict__ m1,
                        const float* __restrict__ v1){
    __shared__ float sinv[C1], sbias[C1];
    __shared__ u32 wmin[8], wmax[8];
    for (int c = threadIdx.x; c < C1; c += blockDim.x){
        float iv = __fdiv_rn(g1[c], __fsqrt_rn(v1[c] + EPSBN));
        sinv[c]  = iv;
        sbias[c] = __fmaf_rn(-m1[c], iv, b1[c]);
    }
    __syncthreads();
    const float4* x4 = (const float4*)x;
    const int tot = NIMG*C1*HW/4;   // 6422528
    float lmin = 3.4e38f, lmax = -3.4e38f;
    for (int i = blockIdx.x*blockDim.x + threadIdx.x; i < tot; i += gridDim.x*blockDim.x){
        int c = (i/196) & (C1-1);
        float iv = sinv[c], bb = sbias[c];
        float4 v = x4[i];
        float a0 = fmaxf(__fmaf_rn(v.x, iv, bb), 0.f);
        float a1 = fmaxf(__fmaf_rn(v.y, iv, bb), 0.f);
        float a2 = fmaxf(__fmaf_rn(v.z, iv, bb), 0.f);
        float a3 = fmaxf(__fmaf_rn(v.w, iv, bb), 0.f);
        lmax = fmaxf(lmax, fmaxf(fmaxf(a0,a1), fmaxf(a2,a3)));
        lmin = fminf(lmin, fminf(fminf(a0,a1), fminf(a2,a3)));
    }
    u32 emin = __reduce_min_sync(0xffffffffu, fenc(lmin));
    u32 emax = __reduce_max_sync(0xffffffffu, fenc(lmax));
    if ((threadIdx.x & 31) == 0){ wmin[threadIdx.x>>5] = emin; wmax[threadIdx.x>>5] = emax; }
    __syncthreads();
    if (threadIdx.x == 0){
        u32 mn = wmin[0], mx = wmax[0];
        for (int i = 1; i < 8; i++){ mn = min(mn, wmin[i]); mx = max(mx, wmax[i]); }
        atomicMin(&g_mm[0], mn); atomicMax(&g_mm[1], mx);
    }
}

// min/max of w1 (block 0) and w2 (block 1)
__global__ void k_mm_w(const float* __restrict__ w1, const float* __restrict__ w2){
    __shared__ u32 wmin[8], wmax[8];
    const float* p = blockIdx.x ? w2 : w1;
    int n    = blockIdx.x ? (C3*C2*9) : (C2*C1);
    int slot = blockIdx.x ? 4 : 2;
    float lmin = 3.4e38f, lmax = -3.4e38f;
    for (int i = threadIdx.x; i < n; i += blockDim.x){
        float v = p[i];
        lmin = fminf(lmin, v); lmax = fmaxf(lmax, v);
    }
    u32 emin = __reduce_min_sync(0xffffffffu, fenc(lmin));
    u32 emax = __reduce_max_sync(0xffffffffu, fenc(lmax));
    if ((threadIdx.x & 31) == 0){ wmin[threadIdx.x>>5] = emin; wmax[threadIdx.x>>5] = emax; }
    __syncthreads();
    if (threadIdx.x == 0){
        u32 mn = wmin[0], mx = wmax[0];
        for (int i = 1; i < 8; i++){ mn = min(mn, wmin[i]); mx = max(mx, wmax[i]); }
        atomicMin(&g_mm[slot], mn); atomicMax(&g_mm[slot+1], mx);
    }
}

__global__ void k_qp(){
    if (threadIdx.x == 0){
        #pragma unroll
        for (int t = 0; t < 3; t++){
            float mn = fdec(g_mm[2*t]), mx = fdec(g_mm[2*t+1]);
            float s = fmaxf(__fdiv_rn(mx - mn, 255.0f), 1e-8f);
            g_qp[3*t] = mn; g_qp[3*t+1] = s; g_qp[3*t+2] = __frcp_rn(s);
        }
    }
}
__global__ void k_qp2(){
    if (threadIdx.x == 0){
        float mn = fdec(g_mm[6]), mx = fdec(g_mm[7]);
        float s = fmaxf(__fdiv_rn(mx - mn, 255.0f), 1e-8f);
        g_qp[9] = mn; g_qp[10] = s; g_qp[11] = __frcp_rn(s);
    }
}

// quantize w1 (one block per co, one thread per u32 group)
__global__ void k_qw1(const float* __restrict__ w1){
    __shared__ int ssum[4];
    int co = blockIdx.x, g = threadIdx.x;  // g in [0,128)
    float mn = g_qp[3], s = g_qp[4], r = g_qp[5];
    u32 pack = 0; int lsum = 0;
    #pragma unroll
    for (int j = 0; j < 4; j++){
        int q = qidx(w1[co*C1 + 4*g + j], mn, s, r);
        pack |= (u32)q << (8*j);
        lsum += q;
    }
    g_wq1_32[co*128 + g] = pack;
    lsum = __reduce_add_sync(0xffffffffu, lsum);
    if ((g & 31) == 0) ssum[g>>5] = lsum;
    __syncthreads();
    if (g == 0) g_ws1[co] = ssum[0] + ssum[1] + ssum[2] + ssum[3];
}

// quantize w2 into transposed layout [tap*32+kg][co], plus per-(co,tap) sums
__global__ void k_qw2(const float* __restrict__ w2){
    __shared__ int sts[9];
    int co = blockIdx.x;
    if (threadIdx.x < 9) sts[threadIdx.x] = 0;
    __syncthreads();
    float mn = g_qp[6], s = g_qp[7], r = g_qp[8];
    for (int f = threadIdx.x; f < 288; f += 128){
        int tap = f / 32, kg = f % 32;
        u32 pack = 0; int psum = 0;
        #pragma unroll
        for (int j = 0; j < 4; j++){
            int ci = kg*4 + j;
            int q = qidx(w2[co*1152 + ci*9 + tap], mn, s, r);
            pack |= (u32)q << (8*j);
            psum += q;
        }
        g_wq2t[(tap*32 + kg)*32 + co] = pack;
        atomicAdd(&sts[tap], psum);
    }
    __syncthreads();
    if (threadIdx.x < 9) g_wts2[co*9 + threadIdx.x] = sts[threadIdx.x];
}

// fused: quantize relu(bn1(x)) tile -> dp4a GEMM vs wq1 -> bn2+relu -> a2 + minmax
__global__ __launch_bounds__(256) void k_conv1(
    const float* __restrict__ x,
    const float* __restrict__ g1, const float* __restrict__ b1,
    const float* __restrict__ m1, const float* __restrict__ v1,
    const float* __restrict__ g2, const float* __restrict__ b2,
    const float* __restrict__ m2, const float* __restrict__ v2)
{
    __shared__ u32 a_s[32*129];      // 16512B: a tile [px][128 groups], stride 129
    __shared__ u32 w_s[128*33];      // 16896B: w chunk [co][32], stride 33
    __shared__ float inv1[C1], bia1[C1];
    __shared__ float inv2[C2], bia2[C2];
    __shared__ int rs[32];
    __shared__ u32 bo[32];
    __shared__ u32 wred[16];

    int tid = threadIdx.x;
    int p0 = blockIdx.x * 32;

    for (int c = tid; c < C1; c += 256){
        float iv = __fdiv_rn(g1[c], __fsqrt_rn(v1[c] + EPSBN));
        inv1[c] = iv; bia1[c] = __fmaf_rn(-m1[c], iv, b1[c]);
    }
    if (tid < C2){
        float iv = __fdiv_rn(g2[tid], __fsqrt_rn(v2[tid] + EPSBN));
        inv2[tid] = iv; bia2[tid] = __fmaf_rn(-m2[tid], iv, b2[tid]);
    }
    if (tid < 32){
        int p = p0 + tid;
        bo[tid] = (u32)((p/HW)*(C1*HW) + (p%HW));
        rs[tid] = 0;
    }
    __syncthreads();

    float mnA = g_qp[0], sA = g_qp[1], rA = g_qp[2];

    // build quantized activation tile
    {
        int px = tid & 31, cg0 = tid >> 5;
        u32 base = bo[px];
        int lsum = 0;
        #pragma unroll
        for (int m = 0; m < 16; m++){
            int g = cg0 + (m << 3);
            u32 pack = 0;
            #pragma unroll
            for (int j = 0; j < 4; j++){
                int ci = 4*g + j;
                float xv = x[base + (u32)ci*HW];
                float a = fmaxf(__fmaf_rn(xv, inv1[ci], bia1[ci]), 0.f);
                int q = qidx(a, mnA, sA, rA);
                pack |= (u32)q << (8*j);
                lsum += q;
            }
            a_s[px*129 + g] = pack;
        }
        atomicAdd(&rs[px], lsum);
    }
    __syncthreads();

    int pg = tid & 7, cg = tid >> 3;       // pixel-group 0..7 (x4), co-group 0..31 (x4)
    u32 acc[4][4] = {};
    for (int kc = 0; kc < 4; kc++){
        #pragma unroll
        for (int it = 0; it < 16; it++){
            int f = it*256 + tid;
            int co = f >> 5, kk = f & 31;
            w_s[co*33 + kk] = g_wq1_32[co*128 + kc*32 + kk];
        }
        __syncthreads();
        #pragma unroll 8
        for (int k = 0; k < 32; k++){
            u32 av[4], wv[4];
            #pragma unroll
            for (int i = 0; i < 4; i++) av[i] = a_s[(pg*4+i)*129 + kc*32 + k];
            #pragma unroll
            for (int j = 0; j < 4; j++) wv[j] = w_s[(cg*4+j)*33 + k];
            #pragma unroll
            for (int i = 0; i < 4; i++)
                #pragma unroll
                for (int j = 0; j < 4; j++)
                    acc[i][j] = __dp4a(av[i], wv[j], acc[i][j]);
        }
        __syncthreads();
    }

    // epilogue: reconstruct fp value, bn2+relu, stage, minmax
    float mnW = g_qp[3], sW = g_qp[4];
    float SS = sA * sW;
    float c0 = 512.0f * mnA * mnW;
    float* fo = (float*)a_s;    // reuse (stride 129 floats)
    float lmax = -3.4e38f, lmin = 3.4e38f;
    #pragma unroll
    for (int i = 0; i < 4; i++){
        int pxi = pg*4 + i;
        float rsum = (float)rs[pxi];
        #pragma unroll
        for (int j = 0; j < 4; j++){
            int co = cg*4 + j;
            float h = SS*(float)acc[i][j] + sA*mnW*rsum + mnA*sW*(float)g_ws1[co] + c0;
            float a2v = fmaxf(__fmaf_rn(h, inv2[co], bia2[co]), 0.f);
            fo[pxi*129 + co] = a2v;
            lmax = fmaxf(lmax, a2v); lmin = fminf(lmin, a2v);
        }
    }
    u32 emin = __reduce_min_sync(0xffffffffu, fenc(lmin));
    u32 emax = __reduce_max_sync(0xffffffffu, fenc(lmax));
    if ((tid & 31) == 0){ wred[tid>>5] = emin; wred[8 + (tid>>5)] = emax; }
    __syncthreads();
    if (tid == 0){
        u32 mn = wred[0], mx = wred[8];
        for (int i = 1; i < 8; i++){ mn = min(mn, wred[i]); mx = max(mx, wred[8+i]); }
        atomicMin(&g_mm[6], mn); atomicMax(&g_mm[7], mx);
    }
    #pragma unroll
    for (int it = 0; it < 16; it++){
        int f = it*256 + tid;
        int pxi = f >> 7, co = f & 127;
        g_a2[(size_t)(p0 + pxi)*C2 + co] = fo[pxi*129 + co];
    }
}

// quantize a2 -> packed u8 NHWC + per-pixel index rowsums
__global__ void k_qa2(){
    int warp = threadIdx.x >> 5, lane = threadIdx.x & 31;
    int p = blockIdx.x*8 + warp;
    float mn = g_qp[9], s = g_qp[10], r = g_qp[11];
    const float4* a4 = (const float4*)&g_a2[(size_t)p*C2];
    float4 v = a4[lane];
    int q0 = qidx(v.x, mn, s, r);
    int q1 = qidx(v.y, mn, s, r);
    int q2 = qidx(v.z, mn, s, r);
    int q3 = qidx(v.w, mn, s, r);
    g_aq2[(size_t)p*32 + lane] = (u32)q0 | ((u32)q1<<8) | ((u32)q2<<16) | ((u32)q3<<24);
    int sum = __reduce_add_sync(0xffffffffu, q0+q1+q2+q3);
    if (lane == 0) g_rs2[p] = sum;
}

// 3x3 conv via dp4a, one block per (image, output row)
__global__ __launch_bounds__(128) void k_conv2(float* __restrict__ out){
    __shared__ u32 w_s[9*32*32];   // [tap*32+kg][co]       36864B
    __shared__ u32 a_t[3*30*32];   // [row][col+1][kg]      11520B (halo cols, zeroed)
    __shared__ int rs_s[3*30];     //                         360B
    int tid = threadIdx.x;
    int b = blockIdx.x;
    int n = b / 28, h = b % 28;

    for (int f = tid; f < 9*32*32; f += 128) w_s[f] = g_wq2t[f];
    for (int f = tid; f < 3*30*32; f += 128) a_t[f] = 0;
    if (tid < 90) rs_s[tid] = 0;
    __syncthreads();
    for (int f = tid; f < 3*28*32; f += 128){
        int rr = f / (28*32); int rem = f - rr*28*32;
        int col = rem >> 5, k = rem & 31;
        int gh = h + rr - 1;
        if ((unsigned)gh < 28u)
            a_t[(rr*30 + col + 1)*32 + k] = g_aq2[(size_t)(n*HW + gh*28 + col)*32 + k];
    }
    if (tid < 84){
        int rr = tid / 28, col = tid % 28;
        int gh = h + rr - 1;
        if ((unsigned)gh < 28u) rs_s[rr*30 + col + 1] = g_rs2[n*HW + gh*28 + col];
    }
    __syncthreads();

    int co = tid & 31, pg = tid >> 5;   // pg 0..3, 7 pixels each
    int pbase = pg * 7;
    u32 acc[7] = {};
    #pragma unroll 4
    for (int k = 0; k < 32; k++){
        u32 wv[9], av[3][9];
        #pragma unroll
        for (int t = 0; t < 9; t++) wv[t] = w_s[(t*32 + k)*32 + co];
        #pragma unroll
        for (int rr = 0; rr < 3; rr++)
            #pragma unroll
            for (int c = 0; c < 9; c++)
                av[rr][c] = a_t[(rr*30 + pbase + c)*32 + k];
        #pragma unroll
        for (int i = 0; i < 7; i++)
            #pragma unroll
            for (int rr = 0; rr < 3; rr++)
                #pragma unroll
                for (int dw = 0; dw < 3; dw++)
                    acc[i] = __dp4a(av[rr][i+dw], wv[rr*3+dw], acc[i]);
    }

    float mnA2 = g_qp[9], sA2 = g_qp[10], mnW = g_qp[6], sW = g_qp[7];
    int rowv = 0;
    #pragma unroll
    for (int rr = 0; rr < 3; rr++) rowv += ((unsigned)(h + rr - 1) < 28u);
    int wts[9];
    #pragma unroll
    for (int t = 0; t < 9; t++) wts[t] = g_wts2[co*9 + t];
    float* obase = out + ((size_t)n*32 + co)*HW + h*28;
    #pragma unroll
    for (int i = 0; i < 7; i++){
        int px = pbase + i;
        int rssum = 0;
        #pragma unroll
        for (int rr = 0; rr < 3; rr++)
            #pragma unroll
            for (int dw = 0; dw < 3; dw++)
                rssum += rs_s[rr*30 + px + dw];
        int wvsum = 0, nvc = 0;
        #pragma unroll
        for (int dw = 0; dw < 3; dw++){
            if ((unsigned)(px + dw - 1) < 28u){
                nvc++;
                #pragma unroll
                for (int rr = 0; rr < 3; rr++)
                    if ((unsigned)(h + rr - 1) < 28u) wvsum += wts[rr*3 + dw];
            }
        }
        int nv = rowv * nvc;
        float o = sA2*sW*(float)(int)acc[i] + sA2*mnW*(float)rssum
                + mnA2*sW*(float)wvsum + mnA2*mnW*128.0f*(float)nv;
        obase[px] = o;
    }
}

extern "C" void kernel_launch(void* const* d_in, const int* in_sizes, int n_in,
                              void* d_out, int out_size){
    const float* x  = (const float*)d_in[0];
    const float* g1 = (const float*)d_in[1];
    const float* b1 = (const float*)d_in[2];
    const float* m1 = (const float*)d_in[3];
    const float* v1 = (const float*)d_in[4];
    const float* w1 = (const float*)d_in[5];
    const float* g2 = (const float*)d_in[6];
    const float* b2 = (const float*)d_in[7];
    const float* m2 = (const float*)d_in[8];
    const float* v2 = (const float*)d_in[9];
    const float* w2 = (const float*)d_in[10];
    float* out = (float*)d_out;

    k_init<<<1, 32>>>();
    k_mm_a1<<<1024, 256>>>(x, g1, b1, m1, v1);
    k_mm_w<<<2, 256>>>(w1, w2);
    k_qp<<<1, 1>>>();
    k_qw1<<<128, 128>>>(w1);
    k_qw2<<<32, 128>>>(w2);
    k_conv1<<<1568, 256>>>(x, g1, b1, m1, v1, g2, b2, m2, v2);
    k_qp2<<<1, 1>>>();
    k_qa2<<<6272, 256>>>();
    k_conv2<<<1792, 128>>>(out);
}